// round 1
// baseline (speedup 1.0000x reference)
#include <cuda_runtime.h>
#include <cuda_bf16.h>
#include <cstdint>

// Problem constants
#define N_ROWS   8192      // 2 * B * S^3
#define C_DIM    16
#define NB_J     16        // j-chunks for logits kernel
#define ESCALE   14.4269504088896340f   // 10 * log2(e): logits/T in log2 domain

// Scratch (device globals: no allocation allowed)
__device__ float g_mm[N_ROWS * C_DIM];       // pooled+flattened [8192][16]
__device__ float g_fu[N_ROWS * C_DIM];       // normalized features
__device__ float g_fs[N_ROWS * C_DIM];       // normalized * ESCALE
__device__ float g_partial[NB_J * N_ROWS];   // partial exp-sums per j-chunk

// ---------------------------------------------------------------------------
// Kernel 1: AdaptiveAvgPool3d(64->8) for both tensors, write [8192][16] fp32.
// Grid: 2048 blocks (tensor, b, c, sd), 256 threads (8 warps = 8 sy slabs).
// Each warp reduces its [8 x 8 x 64] slab with fully-coalesced 512B LDG.128
// bursts, then 4-lane shuffle groups produce the 8 sx outputs.
// ---------------------------------------------------------------------------
__global__ void __launch_bounds__(256) pool_kernel(const float* __restrict__ p1,
                                                   const float* __restrict__ p2)
{
    int bid = blockIdx.x;            // 0..2047
    int t   = bid >> 10;             // tensor select
    int r   = bid & 1023;
    int b   = r >> 7;
    int c   = (r >> 3) & 15;
    int sd  = r & 7;

    const float* p = t ? p2 : p1;
    int tid    = threadIdx.x;
    int sh     = tid >> 5;           // warp id == sy
    int lane   = tid & 31;
    int rowsel = lane >> 4;          // which h row of the pair
    int wid4   = lane & 15;          // float4 index within 64-float row

    // element base: ((b*16 + c)*64 + sd*8)*4096 + (sh*8)*64  (div by 4 -> float4)
    const float4* base = (const float4*)(p + ((((b << 4) + c) * 64 + (sd << 3)) << 12)
                                           + (sh << 3) * 64);

    float acc = 0.f;
#pragma unroll
    for (int dz = 0; dz < 8; dz++) {
#pragma unroll
        for (int hp = 0; hp < 4; hp++) {
            float4 v = base[dz * 1024 + (hp * 2 + rowsel) * 16 + wid4];
            acc += (v.x + v.y) + (v.z + v.w);
        }
    }
    // lanes {2s, 2s+1, 16+2s, 16+2s+1} share sx = s
    acc += __shfl_xor_sync(0xffffffffu, acc, 1);
    acc += __shfl_xor_sync(0xffffffffu, acc, 16);

    if (((lane & 1) == 0) && lane < 16) {
        int sx  = lane >> 1;
        int row = t * 4096 + b * 512 + sd * 64 + sh * 8 + sx;
        g_mm[row * C_DIM + c] = acc * (1.0f / 512.0f);
    }
}

// ---------------------------------------------------------------------------
// Kernel 2: project_head (Linear->ReLU->Linear) + F.normalize per row.
// Writes g_fu (unit features) and g_fs (unit features * 10*log2e).
// ---------------------------------------------------------------------------
__global__ void __launch_bounds__(256) mlp_kernel(const float* __restrict__ w1,
                                                  const float* __restrict__ b1,
                                                  const float* __restrict__ w2,
                                                  const float* __restrict__ b2)
{
    __shared__ float sw1[256], sw2[256], sb1[16], sb2[16];
    int tid = threadIdx.x;
    sw1[tid] = w1[tid];
    sw2[tid] = w2[tid];
    if (tid < 16) { sb1[tid] = b1[tid]; sb2[tid] = b2[tid]; }
    __syncthreads();

    int row = blockIdx.x * 256 + tid;

    float x[16];
    const float4* mm4 = (const float4*)(g_mm + row * C_DIM);
#pragma unroll
    for (int q = 0; q < 4; q++) {
        float4 v = mm4[q];
        x[q * 4 + 0] = v.x; x[q * 4 + 1] = v.y; x[q * 4 + 2] = v.z; x[q * 4 + 3] = v.w;
    }

    float h[16];
#pragma unroll
    for (int k = 0; k < 16; k++) {
        float s = sb1[k];
#pragma unroll
        for (int cc = 0; cc < 16; cc++) s = fmaf(sw1[k * 16 + cc], x[cc], s);
        h[k] = fmaxf(s, 0.f);
    }

    float f[16];
    float nsq = 0.f;
#pragma unroll
    for (int k = 0; k < 16; k++) {
        float s = sb2[k];
#pragma unroll
        for (int cc = 0; cc < 16; cc++) s = fmaf(sw2[k * 16 + cc], h[cc], s);
        f[k] = s;
        nsq = fmaf(s, s, nsq);
    }
    float inv = 1.0f / fmaxf(sqrtf(nsq), 1e-12f);

    float4* fu4 = (float4*)(g_fu + row * C_DIM);
    float4* fs4 = (float4*)(g_fs + row * C_DIM);
#pragma unroll
    for (int q = 0; q < 4; q++) {
        float4 u;
        u.x = f[q * 4 + 0] * inv; u.y = f[q * 4 + 1] * inv;
        u.z = f[q * 4 + 2] * inv; u.w = f[q * 4 + 3] * inv;
        fu4[q] = u;
        float4 s2;
        s2.x = u.x * ESCALE; s2.y = u.y * ESCALE; s2.z = u.z * ESCALE; s2.w = u.w * ESCALE;
        fs4[q] = s2;
    }
}

// ---------------------------------------------------------------------------
// Packed f32x2 helpers (Blackwell: fma.rn.f32x2 doubles FFMA throughput)
// ---------------------------------------------------------------------------
__device__ __forceinline__ unsigned long long fma2(unsigned long long a,
                                                   unsigned long long b,
                                                   unsigned long long c)
{
    unsigned long long d;
    asm("fma.rn.f32x2 %0, %1, %2, %3;" : "=l"(d) : "l"(a), "l"(b), "l"(c));
    return d;
}
__device__ __forceinline__ unsigned long long mul2(unsigned long long a,
                                                   unsigned long long b)
{
    unsigned long long d;
    asm("mul.rn.f32x2 %0, %1, %2;" : "=l"(d) : "l"(a), "l"(b));
    return d;
}
__device__ __forceinline__ float sum2(unsigned long long a)
{
    float lo, hi;
    asm("mov.b64 {%0, %1}, %2;" : "=f"(lo), "=f"(hi) : "l"(a));
    return lo + hi;
}
__device__ __forceinline__ float ex2_approx(float x)
{
    float r;
    asm("ex2.approx.f32 %0, %1;" : "=f"(r) : "f"(x));
    return r;
}

// ---------------------------------------------------------------------------
// Kernel 3: partial exp-sums of the NxN similarity matrix (diagonal skipped).
// Grid (32, 16) x 128 threads. Each thread carries TWO i-rows (g_fs, already
// scaled to log2 domain) in registers; j tiles of 128 rows of g_fu broadcast
// from shared. dot(fs_i, fu_j) == logit*log2e -> one ex2.approx per pair.
// Each block writes its own g_partial slot: race-free, deterministic.
// ---------------------------------------------------------------------------
__global__ void __launch_bounds__(128) logits_kernel()
{
    __shared__ ulonglong2 sj[128 * 4];   // 128 j-rows * 16 floats = 8 KB
    int tid = threadIdx.x;
    int ib  = blockIdx.x;                // 0..31  -> i tile of 256
    int jb  = blockIdx.y;                // 0..15  -> j chunk of 512

    int i0 = ib * 256 + tid;
    int i1 = i0 + 128;

    ulonglong2 A0[4], A1[4];
    const ulonglong2* fs = (const ulonglong2*)g_fs;
#pragma unroll
    for (int q = 0; q < 4; q++) { A0[q] = fs[i0 * 4 + q]; A1[q] = fs[i1 * 4 + q]; }

    const ulonglong2* fu = (const ulonglong2*)g_fu;
    float sum0 = 0.f, sum1 = 0.f;
    int jch = jb * 512;

    for (int tph = 0; tph < 4; tph++) {
        int j0 = jch + tph * 128;
        __syncthreads();
#pragma unroll
        for (int q = 0; q < 4; q++) sj[tid * 4 + q] = fu[(j0 + tid) * 4 + q];
        __syncthreads();

#pragma unroll 4
        for (int jj = 0; jj < 128; jj++) {
            ulonglong2 B0 = sj[jj * 4 + 0];
            ulonglong2 B1 = sj[jj * 4 + 1];
            ulonglong2 B2 = sj[jj * 4 + 2];
            ulonglong2 B3 = sj[jj * 4 + 3];

            unsigned long long acc0 = mul2(A0[0].x, B0.x);
            acc0 = fma2(A0[0].y, B0.y, acc0);
            acc0 = fma2(A0[1].x, B1.x, acc0);
            acc0 = fma2(A0[1].y, B1.y, acc0);
            acc0 = fma2(A0[2].x, B2.x, acc0);
            acc0 = fma2(A0[2].y, B2.y, acc0);
            acc0 = fma2(A0[3].x, B3.x, acc0);
            acc0 = fma2(A0[3].y, B3.y, acc0);

            unsigned long long acc1 = mul2(A1[0].x, B0.x);
            acc1 = fma2(A1[0].y, B0.y, acc1);
            acc1 = fma2(A1[1].x, B1.x, acc1);
            acc1 = fma2(A1[1].y, B1.y, acc1);
            acc1 = fma2(A1[2].x, B2.x, acc1);
            acc1 = fma2(A1[2].y, B2.y, acc1);
            acc1 = fma2(A1[3].x, B3.x, acc1);
            acc1 = fma2(A1[3].y, B3.y, acc1);

            float e0 = ex2_approx(sum2(acc0));
            float e1 = ex2_approx(sum2(acc1));
            int jg = j0 + jj;
            if (jg != i0) sum0 += e0;
            if (jg != i1) sum1 += e1;
        }
    }

    g_partial[jb * N_ROWS + i0] = sum0;
    g_partial[jb * N_ROWS + i1] = sum1;
}

// ---------------------------------------------------------------------------
// Kernel 4: per-row lse = log(sum of partials), pos = 10 * <f_i, f_{i+4096}>,
// mean(lse - pos) -> scalar output.
// ---------------------------------------------------------------------------
__global__ void __launch_bounds__(1024) final_kernel(float* __restrict__ out)
{
    __shared__ float red[1024];
    int tid = threadIdx.x;
    float local = 0.f;

    for (int i = tid; i < N_ROWS; i += 1024) {
        float S = 0.f;
#pragma unroll
        for (int jb = 0; jb < NB_J; jb++) S += g_partial[jb * N_ROWS + i];

        int p = (i + 4096) & (N_ROWS - 1);
        const float* a  = g_fu + i * C_DIM;
        const float* bb = g_fu + p * C_DIM;
        float dot = 0.f;
#pragma unroll
        for (int k = 0; k < 16; k++) dot = fmaf(a[k], bb[k], dot);

        local += logf(S) - 10.0f * dot;
    }

    red[tid] = local;
    __syncthreads();
    for (int s = 512; s > 0; s >>= 1) {
        if (tid < s) red[tid] += red[tid + s];
        __syncthreads();
    }
    if (tid == 0) out[0] = red[0] * (1.0f / (float)N_ROWS);
}

// ---------------------------------------------------------------------------
extern "C" void kernel_launch(void* const* d_in, const int* in_sizes, int n_in,
                              void* d_out, int out_size)
{
    const float* p1 = (const float*)d_in[0];
    const float* p2 = (const float*)d_in[1];
    const float* w1 = (const float*)d_in[2];
    const float* b1 = (const float*)d_in[3];
    const float* w2 = (const float*)d_in[4];
    const float* b2 = (const float*)d_in[5];

    pool_kernel<<<2048, 256>>>(p1, p2);
    mlp_kernel<<<32, 256>>>(w1, b1, w2, b2);
    logits_kernel<<<dim3(32, 16), 128>>>();
    final_kernel<<<1, 1024>>>((float*)d_out);
}

// round 2
// speedup vs baseline: 1.5156x; 1.5156x over previous
#include <cuda_runtime.h>
#include <cuda_bf16.h>
#include <cstdint>

// Problem constants
#define N_ROWS   8192      // 2 * B * S^3
#define C_DIM    16
#define NB_J     16        // j-chunks for logits kernel
#define ESCALE   14.4269504088896340f   // 10 * log2(e): logits/T in log2 domain

// Scratch (device globals: no allocation allowed)
__device__ float g_mm[N_ROWS * C_DIM];       // pooled+flattened [8192][16]
__device__ float g_fu[N_ROWS * C_DIM];       // normalized features
__device__ float g_fs[N_ROWS * C_DIM];       // normalized * ESCALE
__device__ float g_partial[NB_J * N_ROWS];   // partial exp-sums per j-chunk
__device__ float g_blocksum[32];             // per-block loss partials

// ---------------------------------------------------------------------------
// Kernel 1: AdaptiveAvgPool3d(64->8) for both tensors, write [8192][16] fp32.
// Grid: 2048 blocks (tensor, b, c, sd), 256 threads (8 warps = 8 sy slabs).
// ---------------------------------------------------------------------------
__global__ void __launch_bounds__(256) pool_kernel(const float* __restrict__ p1,
                                                   const float* __restrict__ p2)
{
    int bid = blockIdx.x;            // 0..2047
    int t   = bid >> 10;             // tensor select
    int r   = bid & 1023;
    int b   = r >> 7;
    int c   = (r >> 3) & 15;
    int sd  = r & 7;

    const float* p = t ? p2 : p1;
    int tid    = threadIdx.x;
    int sh     = tid >> 5;           // warp id == sy
    int lane   = tid & 31;
    int rowsel = lane >> 4;          // which h row of the pair
    int wid4   = lane & 15;          // float4 index within 64-float row

    const float4* base = (const float4*)(p + ((((b << 4) + c) * 64 + (sd << 3)) << 12)
                                           + (sh << 3) * 64);

    float acc = 0.f;
#pragma unroll
    for (int dz = 0; dz < 8; dz++) {
#pragma unroll
        for (int hp = 0; hp < 4; hp++) {
            float4 v = base[dz * 1024 + (hp * 2 + rowsel) * 16 + wid4];
            acc += (v.x + v.y) + (v.z + v.w);
        }
    }
    acc += __shfl_xor_sync(0xffffffffu, acc, 1);
    acc += __shfl_xor_sync(0xffffffffu, acc, 16);

    if (((lane & 1) == 0) && lane < 16) {
        int sx  = lane >> 1;
        int row = t * 4096 + b * 512 + sd * 64 + sh * 8 + sx;
        g_mm[row * C_DIM + c] = acc * (1.0f / 512.0f);
    }
}

// ---------------------------------------------------------------------------
// Kernel 2: project_head (Linear->ReLU->Linear) + F.normalize per row.
// ---------------------------------------------------------------------------
__global__ void __launch_bounds__(256) mlp_kernel(const float* __restrict__ w1,
                                                  const float* __restrict__ b1,
                                                  const float* __restrict__ w2,
                                                  const float* __restrict__ b2)
{
    __shared__ float sw1[256], sw2[256], sb1[16], sb2[16];
    int tid = threadIdx.x;
    sw1[tid] = w1[tid];
    sw2[tid] = w2[tid];
    if (tid < 16) { sb1[tid] = b1[tid]; sb2[tid] = b2[tid]; }
    __syncthreads();

    int row = blockIdx.x * 256 + tid;

    float x[16];
    const float4* mm4 = (const float4*)(g_mm + row * C_DIM);
#pragma unroll
    for (int q = 0; q < 4; q++) {
        float4 v = mm4[q];
        x[q * 4 + 0] = v.x; x[q * 4 + 1] = v.y; x[q * 4 + 2] = v.z; x[q * 4 + 3] = v.w;
    }

    float h[16];
#pragma unroll
    for (int k = 0; k < 16; k++) {
        float s = sb1[k];
#pragma unroll
        for (int cc = 0; cc < 16; cc++) s = fmaf(sw1[k * 16 + cc], x[cc], s);
        h[k] = fmaxf(s, 0.f);
    }

    float f[16];
    float nsq = 0.f;
#pragma unroll
    for (int k = 0; k < 16; k++) {
        float s = sb2[k];
#pragma unroll
        for (int cc = 0; cc < 16; cc++) s = fmaf(sw2[k * 16 + cc], h[cc], s);
        f[k] = s;
        nsq = fmaf(s, s, nsq);
    }
    float inv = 1.0f / fmaxf(sqrtf(nsq), 1e-12f);

    float4* fu4 = (float4*)(g_fu + row * C_DIM);
    float4* fs4 = (float4*)(g_fs + row * C_DIM);
#pragma unroll
    for (int q = 0; q < 4; q++) {
        float4 u;
        u.x = f[q * 4 + 0] * inv; u.y = f[q * 4 + 1] * inv;
        u.z = f[q * 4 + 2] * inv; u.w = f[q * 4 + 3] * inv;
        fu4[q] = u;
        float4 s2;
        s2.x = u.x * ESCALE; s2.y = u.y * ESCALE; s2.z = u.z * ESCALE; s2.w = u.w * ESCALE;
        fs4[q] = s2;
    }
}

// ---------------------------------------------------------------------------
// Packed f32x2 helpers (Blackwell: fma.rn.f32x2 doubles FFMA throughput)
// ---------------------------------------------------------------------------
__device__ __forceinline__ unsigned long long fma2(unsigned long long a,
                                                   unsigned long long b,
                                                   unsigned long long c)
{
    unsigned long long d;
    asm("fma.rn.f32x2 %0, %1, %2, %3;" : "=l"(d) : "l"(a), "l"(b), "l"(c));
    return d;
}
__device__ __forceinline__ unsigned long long mul2(unsigned long long a,
                                                   unsigned long long b)
{
    unsigned long long d;
    asm("mul.rn.f32x2 %0, %1, %2;" : "=l"(d) : "l"(a), "l"(b));
    return d;
}
__device__ __forceinline__ float sum2(unsigned long long a)
{
    float lo, hi;
    asm("mov.b64 {%0, %1}, %2;" : "=f"(lo), "=f"(hi) : "l"(a));
    return lo + hi;
}
__device__ __forceinline__ float ex2_approx(float x)
{
    float r;
    asm("ex2.approx.f32 %0, %1;" : "=f"(r) : "f"(x));
    return r;
}

// ---------------------------------------------------------------------------
// Kernel 3: partial exp-sums of the NxN similarity matrix (diagonal skipped).
// Grid (32, 16) x 128 threads; each thread carries TWO i-rows in registers.
// ---------------------------------------------------------------------------
__global__ void __launch_bounds__(128) logits_kernel()
{
    __shared__ ulonglong2 sj[128 * 4];   // 128 j-rows * 16 floats = 8 KB
    int tid = threadIdx.x;
    int ib  = blockIdx.x;                // 0..31  -> i tile of 256
    int jb  = blockIdx.y;                // 0..15  -> j chunk of 512

    int i0 = ib * 256 + tid;
    int i1 = i0 + 128;

    ulonglong2 A0[4], A1[4];
    const ulonglong2* fs = (const ulonglong2*)g_fs;
#pragma unroll
    for (int q = 0; q < 4; q++) { A0[q] = fs[i0 * 4 + q]; A1[q] = fs[i1 * 4 + q]; }

    const ulonglong2* fu = (const ulonglong2*)g_fu;
    float sum0 = 0.f, sum1 = 0.f;
    int jch = jb * 512;

    for (int tph = 0; tph < 4; tph++) {
        int j0 = jch + tph * 128;
        __syncthreads();
#pragma unroll
        for (int q = 0; q < 4; q++) sj[tid * 4 + q] = fu[(j0 + tid) * 4 + q];
        __syncthreads();

#pragma unroll 4
        for (int jj = 0; jj < 128; jj++) {
            ulonglong2 B0 = sj[jj * 4 + 0];
            ulonglong2 B1 = sj[jj * 4 + 1];
            ulonglong2 B2 = sj[jj * 4 + 2];
            ulonglong2 B3 = sj[jj * 4 + 3];

            unsigned long long acc0 = mul2(A0[0].x, B0.x);
            acc0 = fma2(A0[0].y, B0.y, acc0);
            acc0 = fma2(A0[1].x, B1.x, acc0);
            acc0 = fma2(A0[1].y, B1.y, acc0);
            acc0 = fma2(A0[2].x, B2.x, acc0);
            acc0 = fma2(A0[2].y, B2.y, acc0);
            acc0 = fma2(A0[3].x, B3.x, acc0);
            acc0 = fma2(A0[3].y, B3.y, acc0);

            unsigned long long acc1 = mul2(A1[0].x, B0.x);
            acc1 = fma2(A1[0].y, B0.y, acc1);
            acc1 = fma2(A1[1].x, B1.x, acc1);
            acc1 = fma2(A1[1].y, B1.y, acc1);
            acc1 = fma2(A1[2].x, B2.x, acc1);
            acc1 = fma2(A1[2].y, B2.y, acc1);
            acc1 = fma2(A1[3].x, B3.x, acc1);
            acc1 = fma2(A1[3].y, B3.y, acc1);

            float e0 = ex2_approx(sum2(acc0));
            float e1 = ex2_approx(sum2(acc1));
            int jg = j0 + jj;
            if (jg != i0) sum0 += e0;
            if (jg != i1) sum1 += e1;
        }
    }

    g_partial[jb * N_ROWS + i0] = sum0;
    g_partial[jb * N_ROWS + i1] = sum1;
}

// ---------------------------------------------------------------------------
// Kernel 4a: per-row lse - pos, reduced within each of 32 blocks (1 row/thread).
// ---------------------------------------------------------------------------
__global__ void __launch_bounds__(256) final_partial_kernel()
{
    __shared__ float red[256];
    int tid = threadIdx.x;
    int i   = blockIdx.x * 256 + tid;    // exactly 8192 threads, one row each

    float S = 0.f;
#pragma unroll
    for (int jb = 0; jb < NB_J; jb++) S += g_partial[jb * N_ROWS + i];

    int p = (i + 4096) & (N_ROWS - 1);
    const float4* a  = (const float4*)(g_fu + i * C_DIM);
    const float4* bb = (const float4*)(g_fu + p * C_DIM);
    float dot = 0.f;
#pragma unroll
    for (int q = 0; q < 4; q++) {
        float4 av = a[q], bv = bb[q];
        dot = fmaf(av.x, bv.x, dot);
        dot = fmaf(av.y, bv.y, dot);
        dot = fmaf(av.z, bv.z, dot);
        dot = fmaf(av.w, bv.w, dot);
    }

    red[tid] = logf(S) - 10.0f * dot;
    __syncthreads();
#pragma unroll
    for (int s = 128; s > 0; s >>= 1) {
        if (tid < s) red[tid] += red[tid + s];
        __syncthreads();
    }
    if (tid == 0) g_blocksum[blockIdx.x] = red[0];
}

// ---------------------------------------------------------------------------
// Kernel 4b: combine 32 block sums -> mean.
// ---------------------------------------------------------------------------
__global__ void __launch_bounds__(32) final_combine_kernel(float* __restrict__ out)
{
    int lane = threadIdx.x;
    float v = g_blocksum[lane];
#pragma unroll
    for (int s = 16; s > 0; s >>= 1) v += __shfl_xor_sync(0xffffffffu, v, s);
    if (lane == 0) out[0] = v * (1.0f / (float)N_ROWS);
}

// ---------------------------------------------------------------------------
extern "C" void kernel_launch(void* const* d_in, const int* in_sizes, int n_in,
                              void* d_out, int out_size)
{
    const float* p1 = (const float*)d_in[0];
    const float* p2 = (const float*)d_in[1];
    const float* w1 = (const float*)d_in[2];
    const float* b1 = (const float*)d_in[3];
    const float* w2 = (const float*)d_in[4];
    const float* b2 = (const float*)d_in[5];

    pool_kernel<<<2048, 256>>>(p1, p2);
    mlp_kernel<<<32, 256>>>(w1, b1, w2, b2);
    logits_kernel<<<dim3(32, 16), 128>>>();
    final_partial_kernel<<<32, 256>>>();
    final_combine_kernel<<<1, 32>>>((float*)d_out);
}

// round 3
// speedup vs baseline: 1.7088x; 1.1274x over previous
#include <cuda_runtime.h>
#include <cuda_bf16.h>
#include <cstdint>

// Problem constants
#define N_ROWS   8192      // 2 * B * S^3
#define C_DIM    16
#define NB_J     32        // j-chunks for logits kernel (chunk = 256 rows)
#define ESCALE   14.4269504088896340f   // 10 * log2(e): logits/T in log2 domain

// Scratch (device globals: no allocation allowed)
__device__ float g_mm[N_ROWS * C_DIM];       // pooled+flattened [8192][16]
__device__ float g_fu[N_ROWS * C_DIM];       // normalized features
__device__ float g_fs[N_ROWS * C_DIM];       // normalized * ESCALE
__device__ float g_partial[NB_J * N_ROWS];   // partial exp-sums per j-chunk
__device__ float g_blocksum[32];             // per-block loss partials

// ---------------------------------------------------------------------------
// Kernel 1: AdaptiveAvgPool3d(64->8) for both tensors, write [8192][16] fp32.
// ---------------------------------------------------------------------------
__global__ void __launch_bounds__(256) pool_kernel(const float* __restrict__ p1,
                                                   const float* __restrict__ p2)
{
    int bid = blockIdx.x;            // 0..2047
    int t   = bid >> 10;             // tensor select
    int r   = bid & 1023;
    int b   = r >> 7;
    int c   = (r >> 3) & 15;
    int sd  = r & 7;

    const float* p = t ? p2 : p1;
    int tid    = threadIdx.x;
    int sh     = tid >> 5;           // warp id == sy
    int lane   = tid & 31;
    int rowsel = lane >> 4;          // which h row of the pair
    int wid4   = lane & 15;          // float4 index within 64-float row

    const float4* base = (const float4*)(p + ((((b << 4) + c) * 64 + (sd << 3)) << 12)
                                           + (sh << 3) * 64);

    float acc = 0.f;
#pragma unroll
    for (int dz = 0; dz < 8; dz++) {
#pragma unroll
        for (int hp = 0; hp < 4; hp++) {
            float4 v = base[dz * 1024 + (hp * 2 + rowsel) * 16 + wid4];
            acc += (v.x + v.y) + (v.z + v.w);
        }
    }
    acc += __shfl_xor_sync(0xffffffffu, acc, 1);
    acc += __shfl_xor_sync(0xffffffffu, acc, 16);

    if (((lane & 1) == 0) && lane < 16) {
        int sx  = lane >> 1;
        int row = t * 4096 + b * 512 + sd * 64 + sh * 8 + sx;
        g_mm[row * C_DIM + c] = acc * (1.0f / 512.0f);
    }
}

// ---------------------------------------------------------------------------
// Kernel 2: project_head (Linear->ReLU->Linear) + F.normalize per row.
// ---------------------------------------------------------------------------
__global__ void __launch_bounds__(256) mlp_kernel(const float* __restrict__ w1,
                                                  const float* __restrict__ b1,
                                                  const float* __restrict__ w2,
                                                  const float* __restrict__ b2)
{
    __shared__ float sw1[256], sw2[256], sb1[16], sb2[16];
    int tid = threadIdx.x;
    sw1[tid] = w1[tid];
    sw2[tid] = w2[tid];
    if (tid < 16) { sb1[tid] = b1[tid]; sb2[tid] = b2[tid]; }
    __syncthreads();

    int row = blockIdx.x * 256 + tid;

    float x[16];
    const float4* mm4 = (const float4*)(g_mm + row * C_DIM);
#pragma unroll
    for (int q = 0; q < 4; q++) {
        float4 v = mm4[q];
        x[q * 4 + 0] = v.x; x[q * 4 + 1] = v.y; x[q * 4 + 2] = v.z; x[q * 4 + 3] = v.w;
    }

    float h[16];
#pragma unroll
    for (int k = 0; k < 16; k++) {
        float s = sb1[k];
#pragma unroll
        for (int cc = 0; cc < 16; cc++) s = fmaf(sw1[k * 16 + cc], x[cc], s);
        h[k] = fmaxf(s, 0.f);
    }

    float f[16];
    float nsq = 0.f;
#pragma unroll
    for (int k = 0; k < 16; k++) {
        float s = sb2[k];
#pragma unroll
        for (int cc = 0; cc < 16; cc++) s = fmaf(sw2[k * 16 + cc], h[cc], s);
        f[k] = s;
        nsq = fmaf(s, s, nsq);
    }
    float inv = 1.0f / fmaxf(sqrtf(nsq), 1e-12f);

    float4* fu4 = (float4*)(g_fu + row * C_DIM);
    float4* fs4 = (float4*)(g_fs + row * C_DIM);
#pragma unroll
    for (int q = 0; q < 4; q++) {
        float4 u;
        u.x = f[q * 4 + 0] * inv; u.y = f[q * 4 + 1] * inv;
        u.z = f[q * 4 + 2] * inv; u.w = f[q * 4 + 3] * inv;
        fu4[q] = u;
        float4 s2;
        s2.x = u.x * ESCALE; s2.y = u.y * ESCALE; s2.z = u.z * ESCALE; s2.w = u.w * ESCALE;
        fs4[q] = s2;
    }
}

// ---------------------------------------------------------------------------
// Packed f32x2 helpers
// ---------------------------------------------------------------------------
__device__ __forceinline__ unsigned long long fma2(unsigned long long a,
                                                   unsigned long long b,
                                                   unsigned long long c)
{
    unsigned long long d;
    asm("fma.rn.f32x2 %0, %1, %2, %3;" : "=l"(d) : "l"(a), "l"(b), "l"(c));
    return d;
}
__device__ __forceinline__ unsigned long long mul2(unsigned long long a,
                                                   unsigned long long b)
{
    unsigned long long d;
    asm("mul.rn.f32x2 %0, %1, %2;" : "=l"(d) : "l"(a), "l"(b));
    return d;
}
__device__ __forceinline__ float sum2(unsigned long long a)
{
    float lo, hi;
    asm("mov.b64 {%0, %1}, %2;" : "=f"(lo), "=f"(hi) : "l"(a));
    return lo + hi;
}
__device__ __forceinline__ float ex2_approx(float x)
{
    float r;
    asm("ex2.approx.f32 %0, %1;" : "=f"(r) : "f"(x));
    return r;
}

// ---------------------------------------------------------------------------
// Kernel 3: partial exp-sums of the NxN similarity matrix.
// Grid (32, 32) x 128 threads -> 1024 blocks (~7 warps/SMSP: hides the FMA
// chain latency). Each thread carries TWO i-rows; j chunk = 256 rows in two
// 128-row shared phases. Diagonal (j==i) handled only in ib==jb blocks.
// ---------------------------------------------------------------------------
__global__ void __launch_bounds__(128) logits_kernel()
{
    __shared__ ulonglong2 sj[128 * 4];   // 128 j-rows * 16 floats = 8 KB
    int tid = threadIdx.x;
    int ib  = blockIdx.x;                // 0..31  -> i tile of 256
    int jb  = blockIdx.y;                // 0..31  -> j chunk of 256

    int i0 = ib * 256 + tid;
    int i1 = i0 + 128;

    ulonglong2 A0[4], A1[4];
    const ulonglong2* fs = (const ulonglong2*)g_fs;
#pragma unroll
    for (int q = 0; q < 4; q++) { A0[q] = fs[i0 * 4 + q]; A1[q] = fs[i1 * 4 + q]; }

    const ulonglong2* fu = (const ulonglong2*)g_fu;
    float sum0 = 0.f, sum1 = 0.f;
    int jch = jb * 256;
    bool diag = (ib == jb);

    for (int tph = 0; tph < 2; tph++) {
        int j0 = jch + tph * 128;
        __syncthreads();
#pragma unroll
        for (int q = 0; q < 4; q++) sj[tid * 4 + q] = fu[(j0 + tid) * 4 + q];
        __syncthreads();

        if (!diag) {
#pragma unroll 4
            for (int jj = 0; jj < 128; jj++) {
                ulonglong2 B0 = sj[jj * 4 + 0];
                ulonglong2 B1 = sj[jj * 4 + 1];
                ulonglong2 B2 = sj[jj * 4 + 2];
                ulonglong2 B3 = sj[jj * 4 + 3];

                unsigned long long acc0 = mul2(A0[0].x, B0.x);
                acc0 = fma2(A0[0].y, B0.y, acc0);
                acc0 = fma2(A0[1].x, B1.x, acc0);
                acc0 = fma2(A0[1].y, B1.y, acc0);
                acc0 = fma2(A0[2].x, B2.x, acc0);
                acc0 = fma2(A0[2].y, B2.y, acc0);
                acc0 = fma2(A0[3].x, B3.x, acc0);
                acc0 = fma2(A0[3].y, B3.y, acc0);

                unsigned long long acc1 = mul2(A1[0].x, B0.x);
                acc1 = fma2(A1[0].y, B0.y, acc1);
                acc1 = fma2(A1[1].x, B1.x, acc1);
                acc1 = fma2(A1[1].y, B1.y, acc1);
                acc1 = fma2(A1[2].x, B2.x, acc1);
                acc1 = fma2(A1[2].y, B2.y, acc1);
                acc1 = fma2(A1[3].x, B3.x, acc1);
                acc1 = fma2(A1[3].y, B3.y, acc1);

                sum0 += ex2_approx(sum2(acc0));
                sum1 += ex2_approx(sum2(acc1));
            }
        } else {
#pragma unroll 4
            for (int jj = 0; jj < 128; jj++) {
                ulonglong2 B0 = sj[jj * 4 + 0];
                ulonglong2 B1 = sj[jj * 4 + 1];
                ulonglong2 B2 = sj[jj * 4 + 2];
                ulonglong2 B3 = sj[jj * 4 + 3];

                unsigned long long acc0 = mul2(A0[0].x, B0.x);
                acc0 = fma2(A0[0].y, B0.y, acc0);
                acc0 = fma2(A0[1].x, B1.x, acc0);
                acc0 = fma2(A0[1].y, B1.y, acc0);
                acc0 = fma2(A0[2].x, B2.x, acc0);
                acc0 = fma2(A0[2].y, B2.y, acc0);
                acc0 = fma2(A0[3].x, B3.x, acc0);
                acc0 = fma2(A0[3].y, B3.y, acc0);

                unsigned long long acc1 = mul2(A1[0].x, B0.x);
                acc1 = fma2(A1[0].y, B0.y, acc1);
                acc1 = fma2(A1[1].x, B1.x, acc1);
                acc1 = fma2(A1[1].y, B1.y, acc1);
                acc1 = fma2(A1[2].x, B2.x, acc1);
                acc1 = fma2(A1[2].y, B2.y, acc1);
                acc1 = fma2(A1[3].x, B3.x, acc1);
                acc1 = fma2(A1[3].y, B3.y, acc1);

                float e0 = ex2_approx(sum2(acc0));
                float e1 = ex2_approx(sum2(acc1));
                int jg = j0 + jj;
                if (jg != i0) sum0 += e0;
                if (jg != i1) sum1 += e1;
            }
        }
    }

    g_partial[jb * N_ROWS + i0] = sum0;
    g_partial[jb * N_ROWS + i1] = sum1;
}

// ---------------------------------------------------------------------------
// Kernel 4a: per-row lse - pos, reduced within each of 32 blocks.
// ---------------------------------------------------------------------------
__global__ void __launch_bounds__(256) final_partial_kernel()
{
    __shared__ float red[256];
    int tid = threadIdx.x;
    int i   = blockIdx.x * 256 + tid;    // exactly 8192 threads, one row each

    float S = 0.f;
#pragma unroll
    for (int jb = 0; jb < NB_J; jb++) S += g_partial[jb * N_ROWS + i];

    int p = (i + 4096) & (N_ROWS - 1);
    const float4* a  = (const float4*)(g_fu + i * C_DIM);
    const float4* bb = (const float4*)(g_fu + p * C_DIM);
    float dot = 0.f;
#pragma unroll
    for (int q = 0; q < 4; q++) {
        float4 av = a[q], bv = bb[q];
        dot = fmaf(av.x, bv.x, dot);
        dot = fmaf(av.y, bv.y, dot);
        dot = fmaf(av.z, bv.z, dot);
        dot = fmaf(av.w, bv.w, dot);
    }

    red[tid] = logf(S) - 10.0f * dot;
    __syncthreads();
#pragma unroll
    for (int s = 128; s > 0; s >>= 1) {
        if (tid < s) red[tid] += red[tid + s];
        __syncthreads();
    }
    if (tid == 0) g_blocksum[blockIdx.x] = red[0];
}

// ---------------------------------------------------------------------------
// Kernel 4b: combine 32 block sums -> mean.
// ---------------------------------------------------------------------------
__global__ void __launch_bounds__(32) final_combine_kernel(float* __restrict__ out)
{
    int lane = threadIdx.x;
    float v = g_blocksum[lane];
#pragma unroll
    for (int s = 16; s > 0; s >>= 1) v += __shfl_xor_sync(0xffffffffu, v, s);
    if (lane == 0) out[0] = v * (1.0f / (float)N_ROWS);
}

// ---------------------------------------------------------------------------
extern "C" void kernel_launch(void* const* d_in, const int* in_sizes, int n_in,
                              void* d_out, int out_size)
{
    const float* p1 = (const float*)d_in[0];
    const float* p2 = (const float*)d_in[1];
    const float* w1 = (const float*)d_in[2];
    const float* b1 = (const float*)d_in[3];
    const float* w2 = (const float*)d_in[4];
    const float* b2 = (const float*)d_in[5];

    pool_kernel<<<2048, 256>>>(p1, p2);
    mlp_kernel<<<32, 256>>>(w1, b1, w2, b2);
    logits_kernel<<<dim3(32, 32), 128>>>();
    final_partial_kernel<<<32, 256>>>();
    final_combine_kernel<<<1, 32>>>((float*)d_out);
}